// round 15
// baseline (speedup 1.0000x reference)
#include <cuda_runtime.h>
#include <cuda_fp16.h>
#include <math.h>

#define D 128
#define SLOPE 0.2f
#define BN_EPS 1e-5f
#define MAXN 50048
#define MAXET 901120

// GEMM tile config: 256-row M tile, full K=128 in smem (fp16)
#define GM_MT 256
#define GM_HS 136   // half-element stride (272B rows: bank stride 4, conflict-free)
#define GM_SMEM_BYTES ((GM_MT * GM_HS + 128 * GM_HS) * 2)

// GAT kernel launch shape: pooled strided warp scheduling
#define GAT_BLOCKS 592
#define GAT_THREADS 256
#define GAT_WARPS (GAT_BLOCKS * (GAT_THREADS / 32))

// ---------------- scratch (static device globals: allocation-free) ----------------
__device__ __align__(16) __half g_xl_h[MAXN * D];   // fp16 source-transform (gathered)
__device__ __align__(16) float g_xr[MAXN * D];
__device__ __align__(16) float g_xres[MAXN * D];
__device__ __align__(16) float g_h[MAXN * D];
__device__ int g_deg[MAXN];
__device__ int g_cursor[MAXN];
__device__ int g_rowptr[MAXN + 1];
__device__ int g_col[MAXET];
__device__ int g_bsum[64];
__device__ double g_dsum[D];
__device__ double g_dsq[D];
__device__ __align__(16) float g_scale[D];
__device__ __align__(16) float g_shift[D];
__device__ int g_ticket;

// int64-vs-int32 probe: odd 32-bit words of the first 8 values all zero => int64.
__device__ __forceinline__ int probe_is64(const unsigned int* __restrict__ p) {
    unsigned int o = 0;
#pragma unroll
    for (int j = 1; j < 16; j += 2) o |= p[j];
    return o == 0u;
}

// ---------------- CSR build ----------------
__global__ void k_count(const void* __restrict__ ei, int E, int N) {
    __shared__ int s64;
    if (threadIdx.x == 0) s64 = probe_is64((const unsigned int*)ei);
    __syncthreads();
    int is64 = s64;
    int t = blockIdx.x * blockDim.x + threadIdx.x;
    int Et = E + N;
    if (t >= Et) return;
    int d;
    if (t < E) {
        d = is64 ? (int)((const long long*)ei)[(long long)E + t]
                 : ((const int*)ei)[E + t];
    } else {
        d = t - E;  // self loop
    }
    atomicAdd(&g_deg[d], 1);
}

__global__ void k_scan1(int N) {
    __shared__ int s[1024];
    int tid = threadIdx.x;
    int i = blockIdx.x * 1024 + tid;
    int v = (i < N) ? g_deg[i] : 0;
    if (i < N) { g_deg[i] = 0; g_cursor[i] = 0; }  // restore zeros for next call
    s[tid] = v;
    __syncthreads();
    for (int off = 1; off < 1024; off <<= 1) {
        int t = 0;
        if (tid >= off) t = s[tid - off];
        __syncthreads();
        if (tid >= off) s[tid] += t;
        __syncthreads();
    }
    if (i < N) g_rowptr[i + 1] = s[tid];
    if (tid == 1023) g_bsum[blockIdx.x] = s[1023];
}

__global__ void k_scan3(int N) {
    __shared__ int sbase;
    if (threadIdx.x == 0) {
        int acc = 0;
        for (int b = 0; b < blockIdx.x; b++) acc += g_bsum[b];
        sbase = acc;
    }
    __syncthreads();
    int i = blockIdx.x * 1024 + threadIdx.x;
    if (i < N) g_rowptr[i + 1] += sbase;
    if (i == 0) g_rowptr[0] = 0;
}

__global__ void k_scatter(const void* __restrict__ ei, int E, int N) {
    __shared__ int s64;
    if (threadIdx.x == 0) s64 = probe_is64((const unsigned int*)ei);
    __syncthreads();
    int is64 = s64;
    int t = blockIdx.x * blockDim.x + threadIdx.x;
    int Et = E + N;
    if (t >= Et) return;
    int s, d;
    if (t < E) {
        if (is64) {
            s = (int)((const long long*)ei)[t];
            d = (int)((const long long*)ei)[(long long)E + t];
        } else {
            s = ((const int*)ei)[t];
            d = ((const int*)ei)[E + t];
        }
    } else {
        s = d = t - E;
    }
    int pos = g_rowptr[d] + atomicAdd(&g_cursor[d], 1);
    g_col[pos] = s;
}

// ---------------- fp16 tensor-core GEMM (m16n8k16, whole-K, single sync) ----------------
// C[M,128] = act(A)[M,128] @ W[128,128] (+bias)
// Block: 512 threads (16 warps, 8x2), C tile 256x128, warp tile 32x64.
// Operand loads fully via ldmatrix: A = x4 (non-trans), B = x4.trans (2 n-tiles/op).
// Inner loop per warp/ks: 2 + 4 LDS-class ops + 16 MMA (was 8 scalar + 8 x2).
__global__ void __launch_bounds__(512, 1)
k_gemm3(const float* __restrict__ A,
        const float* __restrict__ W0, const float* __restrict__ W1,
        const float* __restrict__ W2,
        void* __restrict__ C0v, void* __restrict__ C1v, float* __restrict__ C2,
        const float* __restrict__ bvec, int M, int affine, int c0half, int c1half) {
    const float* W = (blockIdx.y == 0) ? W0 : (blockIdx.y == 1 ? W1 : W2);
    void* Cv = (blockIdx.y == 0) ? C0v : (blockIdx.y == 1 ? C1v : (void*)C2);
    int ishalf = (blockIdx.y == 0) ? c0half : (blockIdx.y == 1 ? c1half : 0);

    extern __shared__ __half smem_h[];
    __half* As = smem_h;                    // [256][GM_HS]  (row-major, k contig)
    __half* Ws = smem_h + GM_MT * GM_HS;    // [128][GM_HS]  (NATURAL: [k][n], n contig)

    int tid = threadIdx.x;
    int warp = tid >> 5;
    int lane = tid & 31;

    // zero BN accumulators for the following fused GAT+BN kernel
    if (blockIdx.x == 0 && blockIdx.y == 0) {
        if (tid < 128) { g_dsum[tid] = 0.0; g_dsq[tid] = 0.0; }
        if (tid == 0) g_ticket = 0;
    }

    int wm = warp >> 1;           // 0..7  -> 32-row slab
    int wn = warp & 1;            // 0..1  -> 64-col slab
    int m0 = blockIdx.x * GM_MT;

    int qr = lane >> 2;           // 0..7
    int qc = lane & 3;            // 0..3

    // ---- load full A tile (256 x 128) -> fp16 ----
#pragma unroll
    for (int it = 0; it < 16; it++) {
        int i = it * 512 + tid;
        int row = i >> 5;
        int col = (i & 31) * 4;
        int gm = m0 + row;
        float4 v = make_float4(0.f, 0.f, 0.f, 0.f);
        if (gm < M) v = *(const float4*)(A + (long long)gm * 128 + col);
        if (affine) {
            float4 sc = *(const float4*)(g_scale + col);
            float4 sh = *(const float4*)(g_shift + col);
            v.x = fmaf(v.x, sc.x, sh.x); v.x = v.x > 0.f ? v.x : v.x * SLOPE;
            v.y = fmaf(v.y, sc.y, sh.y); v.y = v.y > 0.f ? v.y : v.y * SLOPE;
            v.z = fmaf(v.z, sc.z, sh.z); v.z = v.z > 0.f ? v.z : v.z * SLOPE;
            v.w = fmaf(v.w, sc.w, sh.w); v.w = v.w > 0.f ? v.w : v.w * SLOPE;
        }
        __half* dst = As + row * GM_HS + col;
        *(__half2*)(dst)     = __floats2half2_rn(v.x, v.y);
        *(__half2*)(dst + 2) = __floats2half2_rn(v.z, v.w);
    }
    // ---- load full W (128 x 128) NATURAL [k][n] -> fp16 (conflict-free stores) ----
#pragma unroll
    for (int it = 0; it < 8; it++) {
        int i = it * 512 + tid;
        int row = i >> 5;              // k index 0..127
        int col = (i & 31) * 4;        // n base
        float4 w = *(const float4*)(W + row * 128 + col);
        __half* dst = Ws + row * GM_HS + col;
        *(__half2*)(dst)     = __floats2half2_rn(w.x, w.y);
        *(__half2*)(dst + 2) = __floats2half2_rn(w.z, w.w);
    }
    __syncthreads();

    float acc[2][8][4];
#pragma unroll
    for (int i = 0; i < 2; i++)
#pragma unroll
        for (int j = 0; j < 8; j++)
#pragma unroll
            for (int k = 0; k < 4; k++) acc[i][j][k] = 0.f;

    // ldmatrix lane-address offsets (bytes)
    unsigned as_base = (unsigned)__cvta_generic_to_shared(As);
    unsigned ws_base = (unsigned)__cvta_generic_to_shared(Ws);
    // A x4: lanes 0-15 -> rows rb+(lane&15) @ kb ; lanes 16-31 -> same rows @ kb+8
    unsigned a_off = (unsigned)(lane & 15) * (GM_HS * 2) + (unsigned)(lane >> 4) * 16;
    // B x4.trans: lanes 0-15 -> k rows kb+(lane&15) @ n0 ; lanes 16-31 -> @ n0+8
    unsigned b_off = (unsigned)(lane & 15) * (GM_HS * 2) + (unsigned)(lane >> 4) * 16;

#pragma unroll
    for (int ks = 0; ks < 8; ks++) {
        int kb = ks * 16;
        unsigned a[2][4];
#pragma unroll
        for (int mi = 0; mi < 2; mi++) {
            int rb = wm * 32 + mi * 16;
            unsigned aaddr = as_base + (unsigned)rb * (GM_HS * 2) + (unsigned)kb * 2 + a_off;
            asm volatile(
                "ldmatrix.sync.aligned.m8n8.x4.shared.b16 {%0,%1,%2,%3}, [%4];\n"
                : "=r"(a[mi][0]), "=r"(a[mi][1]), "=r"(a[mi][2]), "=r"(a[mi][3])
                : "r"(aaddr));
        }
        unsigned kaddr = ws_base + (unsigned)kb * (GM_HS * 2) + b_off;
#pragma unroll
        for (int np = 0; np < 4; np++) {          // n-tile pairs: ni = 2np, 2np+1
            int n0 = wn * 64 + np * 16;
            unsigned b0, b1, b2, b3;
            asm volatile(
                "ldmatrix.sync.aligned.m8n8.x4.trans.shared.b16 {%0,%1,%2,%3}, [%4];\n"
                : "=r"(b0), "=r"(b1), "=r"(b2), "=r"(b3)
                : "r"(kaddr + (unsigned)(n0 * 2)));
#pragma unroll
            for (int mi = 0; mi < 2; mi++) {
                asm volatile(
                    "mma.sync.aligned.m16n8k16.row.col.f32.f16.f16.f32 "
                    "{%0,%1,%2,%3}, {%4,%5,%6,%7}, {%8,%9}, {%0,%1,%2,%3};\n"
                    : "+f"(acc[mi][2 * np][0]), "+f"(acc[mi][2 * np][1]),
                      "+f"(acc[mi][2 * np][2]), "+f"(acc[mi][2 * np][3])
                    : "r"(a[mi][0]), "r"(a[mi][1]), "r"(a[mi][2]), "r"(a[mi][3]),
                      "r"(b0), "r"(b1));
                asm volatile(
                    "mma.sync.aligned.m16n8k16.row.col.f32.f16.f16.f32 "
                    "{%0,%1,%2,%3}, {%4,%5,%6,%7}, {%8,%9}, {%0,%1,%2,%3};\n"
                    : "+f"(acc[mi][2 * np + 1][0]), "+f"(acc[mi][2 * np + 1][1]),
                      "+f"(acc[mi][2 * np + 1][2]), "+f"(acc[mi][2 * np + 1][3])
                    : "r"(a[mi][0]), "r"(a[mi][1]), "r"(a[mi][2]), "r"(a[mi][3]),
                      "r"(b2), "r"(b3));
            }
        }
    }

    // epilogue (accumulator layout identical to before)
    float* C = (float*)Cv;
    __half* Ch = (__half*)Cv;
#pragma unroll
    for (int mi = 0; mi < 2; mi++) {
        int r0 = m0 + wm * 32 + mi * 16 + qr;
#pragma unroll
        for (int ni = 0; ni < 8; ni++) {
            int col = wn * 64 + ni * 8 + qc * 2;
            float bx = 0.f, by = 0.f;
            if (bvec) { bx = bvec[col]; by = bvec[col + 1]; }
            if (ishalf) {
                if (r0 < M) {
                    __half2 o = __floats2half2_rn(acc[mi][ni][0] + bx, acc[mi][ni][1] + by);
                    *(__half2*)(Ch + (long long)r0 * 128 + col) = o;
                }
                if (r0 + 8 < M) {
                    __half2 o = __floats2half2_rn(acc[mi][ni][2] + bx, acc[mi][ni][3] + by);
                    *(__half2*)(Ch + (long long)(r0 + 8) * 128 + col) = o;
                }
            } else {
                if (r0 < M) {
                    float2 o; o.x = acc[mi][ni][0] + bx; o.y = acc[mi][ni][1] + by;
                    *(float2*)(C + (long long)r0 * 128 + col) = o;
                }
                if (r0 + 8 < M) {
                    float2 o; o.x = acc[mi][ni][2] + bx; o.y = acc[mi][ni][3] + by;
                    *(float2*)(C + (long long)(r0 + 8) * 128 + col) = o;
                }
            }
        }
    }
}

// ---------------- fused GATv2 edge pass + BN statistics + BN finalize ----------------
// R8 measured-best configuration: xl fp16 (gathered), xr/xres fp32 (streamed).
// Softmax without running max (scores bounded; clamp at 80 for overflow safety).
// NOTE: occupancy-critical at the 64-reg/4-CTA cliff — do not add live registers.
__device__ __forceinline__ float4 ld_h4(const __half* __restrict__ p,
                                        long long node, int lane) {
    uint2 raw = *(const uint2*)(p + node * D + lane * 4);
    float2 f01 = __half22float2(*(__half2*)&raw.x);
    float2 f23 = __half22float2(*(__half2*)&raw.y);
    return make_float4(f01.x, f01.y, f23.x, f23.y);
}

__device__ __forceinline__ float gat_score(float4 ml, float4 xr4, float4 a4) {
    float px = ml.x + xr4.x; px = px > 0.f ? px : px * SLOPE;
    float py = ml.y + xr4.y; py = py > 0.f ? py : py * SLOPE;
    float pz = ml.z + xr4.z; pz = pz > 0.f ? pz : pz * SLOPE;
    float pw = ml.w + xr4.w; pw = pw > 0.f ? pw : pw * SLOPE;
    return px * a4.x + py * a4.y + pz * a4.z + pw * a4.w;
}

__global__ void __launch_bounds__(GAT_THREADS)
k_gat_bn(const __half* __restrict__ xl, const float* __restrict__ xr,
         const float* __restrict__ xres, const float* __restrict__ att,
         const float* __restrict__ bias,
         const float* __restrict__ gamma, const float* __restrict__ beta,
         float* __restrict__ h, int N) {
    __shared__ float s_sum[128];
    __shared__ float s_sq[128];
    __shared__ int s_last;

    int tid = threadIdx.x;
    if (tid < 128) { s_sum[tid] = 0.f; s_sq[tid] = 0.f; }
    __syncthreads();

    int gwarp = blockIdx.x * (GAT_THREADS / 32) + (tid >> 5);
    int lane = tid & 31;

    float4 a4 = *(const float4*)(att + lane * 4);
    float4 b4 = *(const float4*)(bias + lane * 4);

    float lsum[4] = {0.f, 0.f, 0.f, 0.f};
    float lsq[4]  = {0.f, 0.f, 0.f, 0.f};

    for (int node = gwarp; node < N; node += GAT_WARPS) {
        float4 xr4 = *(const float4*)(xr + (long long)node * D + lane * 4);
        int beg = g_rowptr[node];
        int end = g_rowptr[node + 1];

        float s = 0.f;
        float4 acc = make_float4(0.f, 0.f, 0.f, 0.f);

        int e = beg;
        for (; e + 4 <= end; e += 4) {
            int si[4];
#pragma unroll
            for (int j = 0; j < 4; j++) si[j] = g_col[e + j];
            float4 ml[4];
#pragma unroll
            for (int j = 0; j < 4; j++) ml[j] = ld_h4(xl, si[j], lane);
            float pt[4];
#pragma unroll
            for (int j = 0; j < 4; j++) pt[j] = gat_score(ml[j], xr4, a4);
#pragma unroll
            for (int j = 0; j < 4; j++) pt[j] += __shfl_xor_sync(0xffffffffu, pt[j], 1);
#pragma unroll
            for (int j = 0; j < 4; j++) pt[j] += __shfl_xor_sync(0xffffffffu, pt[j], 2);
#pragma unroll
            for (int j = 0; j < 4; j++) pt[j] += __shfl_xor_sync(0xffffffffu, pt[j], 4);
            float p[4];
#pragma unroll
            for (int j = 0; j < 4; j++) p[j] = __expf(fminf(pt[j], 80.f));
#pragma unroll
            for (int j = 0; j < 4; j++) {
                s += p[j];
                acc.x = fmaf(p[j], ml[j].x, acc.x);
                acc.y = fmaf(p[j], ml[j].y, acc.y);
                acc.z = fmaf(p[j], ml[j].z, acc.z);
                acc.w = fmaf(p[j], ml[j].w, acc.w);
            }
        }
        for (; e < end; e++) {
            int s0 = g_col[e];
            float4 ml0 = ld_h4(xl, s0, lane);
            float pt = gat_score(ml0, xr4, a4);
            pt += __shfl_xor_sync(0xffffffffu, pt, 1);
            pt += __shfl_xor_sync(0xffffffffu, pt, 2);
            pt += __shfl_xor_sync(0xffffffffu, pt, 4);
            float p = __expf(fminf(pt, 80.f));
            s += p;
            acc.x = fmaf(p, ml0.x, acc.x);
            acc.y = fmaf(p, ml0.y, acc.y);
            acc.z = fmaf(p, ml0.z, acc.z);
            acc.w = fmaf(p, ml0.w, acc.w);
        }

        float inv = 1.f / s;
        float4 r4 = *(const float4*)(xres + (long long)node * D + lane * 4);
        float4 o;
        o.x = acc.x * inv + b4.x + r4.x;
        o.y = acc.y * inv + b4.y + r4.y;
        o.z = acc.z * inv + b4.z + r4.z;
        o.w = acc.w * inv + b4.w + r4.w;
        *(float4*)(h + (long long)node * D + lane * 4) = o;

        lsum[0] += o.x; lsq[0] += o.x * o.x;
        lsum[1] += o.y; lsq[1] += o.y * o.y;
        lsum[2] += o.z; lsq[2] += o.z * o.z;
        lsum[3] += o.w; lsq[3] += o.w * o.w;
    }

    int c = lane * 4;
#pragma unroll
    for (int j = 0; j < 4; j++) {
        atomicAdd(&s_sum[c + j], lsum[j]);
        atomicAdd(&s_sq[c + j],  lsq[j]);
    }
    __syncthreads();

    if (tid < 128) {
        atomicAdd(&g_dsum[tid], (double)s_sum[tid]);
        atomicAdd(&g_dsq[tid],  (double)s_sq[tid]);
    }
    __threadfence();
    __syncthreads();
    if (tid == 0) {
        int t = atomicAdd(&g_ticket, 1);
        s_last = (t == (int)gridDim.x - 1) ? 1 : 0;
    }
    __syncthreads();

    if (s_last && tid < 128) {
        double mean = __ldcg(&g_dsum[tid]) / (double)N;
        double var  = __ldcg(&g_dsq[tid]) / (double)N - mean * mean;
        float inv = rsqrtf((float)var + BN_EPS);
        float sc = gamma[tid] * inv;
        g_scale[tid] = sc;
        g_shift[tid] = beta[tid] - (float)mean * sc;
    }
}

// ---------------- launch ----------------
extern "C" void kernel_launch(void* const* d_in, const int* in_sizes, int n_in,
                              void* d_out, int out_size) {
    const float* x     = (const float*)d_in[0];
    const void*  ei    = d_in[1];
    const float* Wl    = (const float*)d_in[2];
    const float* Wr    = (const float*)d_in[3];
    const float* att   = (const float*)d_in[4];
    const float* bias  = (const float*)d_in[5];
    const float* Wres  = (const float*)d_in[6];
    const float* gamma = (const float*)d_in[7];
    const float* beta  = (const float*)d_in[8];
    const float* Wout  = (const float*)d_in[9];
    const float* bout  = (const float*)d_in[10];
    int N = in_sizes[0] / D;
    int E = in_sizes[1] / 2;
    float* out = (float*)d_out;

    __half* p_xlh;
    float *p_xr, *p_xres, *p_h;
    cudaGetSymbolAddress((void**)&p_xlh, g_xl_h);
    cudaGetSymbolAddress((void**)&p_xr, g_xr);
    cudaGetSymbolAddress((void**)&p_xres, g_xres);
    cudaGetSymbolAddress((void**)&p_h, g_h);

    static cudaStream_t s2 = []() {
        cudaStream_t s; cudaStreamCreateWithFlags(&s, cudaStreamNonBlocking); return s;
    }();
    static cudaEvent_t ev_fork = []() {
        cudaEvent_t e; cudaEventCreateWithFlags(&e, cudaEventDisableTiming); return e;
    }();
    static cudaEvent_t ev_csr = []() {
        cudaEvent_t e; cudaEventCreateWithFlags(&e, cudaEventDisableTiming); return e;
    }();
    static bool attr_ok = []() {
        cudaFuncSetAttribute(k_gemm3, cudaFuncAttributeMaxDynamicSharedMemorySize,
                             GM_SMEM_BYTES);
        return true;
    }();
    (void)attr_ok;

    int Et = E + N;
    int nb = (N + 1023) / 1024;

    int mtiles = (N + GM_MT - 1) / GM_MT;
    dim3 g3(mtiles, 3);
    dim3 g1(mtiles, 1);

    // fork: CSR build on s2, overlapped with layer-0 GEMM on the main stream
    cudaEventRecord(ev_fork, 0);
    k_gemm3<<<g3, 512, GM_SMEM_BYTES>>>(x, Wl, Wr, Wres,
                                        p_xlh, p_xr, p_xres, nullptr, N, 0, 1, 0);
    cudaStreamWaitEvent(s2, ev_fork, 0);
    k_count<<<(Et + 255) / 256, 256, 0, s2>>>(ei, E, N);
    k_scan1<<<nb, 1024, 0, s2>>>(N);
    k_scan3<<<nb, 1024, 0, s2>>>(N);
    k_scatter<<<(Et + 255) / 256, 256, 0, s2>>>(ei, E, N);
    cudaEventRecord(ev_csr, s2);
    cudaStreamWaitEvent(0, ev_csr, 0);  // join CSR before first edge pass

    const float* xin = x;
    for (int l = 0; l < 3; l++) {
        if (l > 0) {
            k_gemm3<<<g3, 512, GM_SMEM_BYTES>>>(xin,
                                                Wl + l * D * D, Wr + l * D * D,
                                                Wres + l * D * D,
                                                p_xlh, p_xr, p_xres, nullptr, N, 1, 1, 0);
        }
        k_gat_bn<<<GAT_BLOCKS, GAT_THREADS>>>(p_xlh, p_xr, p_xres, att + l * D,
                                              bias + l * D, gamma + l * D,
                                              beta + l * D, p_h, N);
        xin = p_h;
    }
    k_gemm3<<<g1, 512, GM_SMEM_BYTES>>>(p_h, Wout, Wout, Wout,
                                        out, out, out, bout, N, 1, 0, 0);
}

// round 16
// speedup vs baseline: 1.0189x; 1.0189x over previous
#include <cuda_runtime.h>
#include <cuda_fp16.h>
#include <math.h>

#define D 128
#define SLOPE 0.2f
#define BN_EPS 1e-5f
#define MAXN 50048
#define MAXET 901120

// GEMM tile config: 256-row M tile, full K=128 in smem (fp16)
#define GM_MT 256
#define GM_HS 136   // half-element stride (272B rows: bank stride 4, conflict-free)
#define GM_SMEM_BYTES ((GM_MT * GM_HS + 128 * GM_HS) * 2)

// GAT kernel launch shape: pooled strided warp scheduling
#define GAT_BLOCKS 592
#define GAT_THREADS 256
#define GAT_WARPS (GAT_BLOCKS * (GAT_THREADS / 32))

// ---------------- scratch (static device globals: allocation-free) ----------------
__device__ __align__(16) __half g_xl_h[MAXN * D];   // fp16 source-transform (gathered)
__device__ __align__(16) float g_xr[MAXN * D];
__device__ __align__(16) float g_xres[MAXN * D];
__device__ __align__(16) float g_h[MAXN * D];
__device__ __align__(16) __half g_w16[10 * D * D];  // pre-converted fp16 weights
__device__ int g_deg[MAXN];
__device__ int g_cursor[MAXN];
__device__ int g_rowptr[MAXN + 1];
__device__ int g_col[MAXET];
__device__ int g_bsum[64];
__device__ double g_dsum[D];
__device__ double g_dsq[D];
__device__ __align__(16) float g_scale[D];
__device__ __align__(16) float g_shift[D];
__device__ int g_ticket;

// int64-vs-int32 probe: odd 32-bit words of the first 8 values all zero => int64.
__device__ __forceinline__ int probe_is64(const unsigned int* __restrict__ p) {
    unsigned int o = 0;
#pragma unroll
    for (int j = 1; j < 16; j += 2) o |= p[j];
    return o == 0u;
}

// ---------------- weight pre-conversion: fp32 -> fp16 (same _rn rounding) --------
// layout in g_w16: [0..3*16384) Wl(l=0..2), [3..6) Wr, [6..9) Wres, [9] Wout
__global__ void k_wconv(const float* __restrict__ Wl, const float* __restrict__ Wr,
                        const float* __restrict__ Wres, const float* __restrict__ Wout) {
    int i = (blockIdx.x * blockDim.x + threadIdx.x) * 2;   // half2 granularity
    int per = 3 * D * D;
    const float* src;
    int off;
    if (i < per)            { src = Wl;   off = i; }
    else if (i < 2 * per)   { src = Wr;   off = i - per; }
    else if (i < 3 * per)   { src = Wres; off = i - 2 * per; }
    else if (i < 3 * per + D * D) { src = Wout; off = i - 3 * per; }
    else return;
    float2 v = *(const float2*)(src + off);
    *(__half2*)(g_w16 + i) = __floats2half2_rn(v.x, v.y);
}

// ---------------- CSR build ----------------
__global__ void k_count(const void* __restrict__ ei, int E, int N) {
    __shared__ int s64;
    if (threadIdx.x == 0) s64 = probe_is64((const unsigned int*)ei);
    __syncthreads();
    int is64 = s64;
    int t = blockIdx.x * blockDim.x + threadIdx.x;
    int Et = E + N;
    if (t >= Et) return;
    int d;
    if (t < E) {
        d = is64 ? (int)((const long long*)ei)[(long long)E + t]
                 : ((const int*)ei)[E + t];
    } else {
        d = t - E;  // self loop
    }
    atomicAdd(&g_deg[d], 1);
}

__global__ void k_scan1(int N) {
    __shared__ int s[1024];
    int tid = threadIdx.x;
    int i = blockIdx.x * 1024 + tid;
    int v = (i < N) ? g_deg[i] : 0;
    if (i < N) { g_deg[i] = 0; g_cursor[i] = 0; }  // restore zeros for next call
    s[tid] = v;
    __syncthreads();
    for (int off = 1; off < 1024; off <<= 1) {
        int t = 0;
        if (tid >= off) t = s[tid - off];
        __syncthreads();
        if (tid >= off) s[tid] += t;
        __syncthreads();
    }
    if (i < N) g_rowptr[i + 1] = s[tid];
    if (tid == 1023) g_bsum[blockIdx.x] = s[1023];
}

__global__ void k_scan3(int N) {
    __shared__ int sbase;
    if (threadIdx.x == 0) {
        int acc = 0;
        for (int b = 0; b < blockIdx.x; b++) acc += g_bsum[b];
        sbase = acc;
    }
    __syncthreads();
    int i = blockIdx.x * 1024 + threadIdx.x;
    if (i < N) g_rowptr[i + 1] += sbase;
    if (i == 0) g_rowptr[0] = 0;
}

__global__ void k_scatter(const void* __restrict__ ei, int E, int N) {
    __shared__ int s64;
    if (threadIdx.x == 0) s64 = probe_is64((const unsigned int*)ei);
    __syncthreads();
    int is64 = s64;
    int t = blockIdx.x * blockDim.x + threadIdx.x;
    int Et = E + N;
    if (t >= Et) return;
    int s, d;
    if (t < E) {
        if (is64) {
            s = (int)((const long long*)ei)[t];
            d = (int)((const long long*)ei)[(long long)E + t];
        } else {
            s = ((const int*)ei)[t];
            d = ((const int*)ei)[E + t];
        }
    } else {
        s = d = t - E;
    }
    int pos = g_rowptr[d] + atomicAdd(&g_cursor[d], 1);
    g_col[pos] = s;
}

// ---------------- fp16 tensor-core GEMM (m16n8k16, whole-K, single sync) ----------------
// C[M,128] = act(A)[M,128] @ W[128,128] (+bias)
// Block: 512 threads (16 warps, 8x2), C tile 256x128, warp tile 32x64.
// W: pre-converted fp16, fetched via cp.async BEFORE the A phase (overlapped).
// Operand loads via ldmatrix (A: x4, B: x4.trans).
__global__ void __launch_bounds__(512, 1)
k_gemm3(const float* __restrict__ A,
        const __half* __restrict__ W0h, const __half* __restrict__ W1h,
        const __half* __restrict__ W2h,
        void* __restrict__ C0v, void* __restrict__ C1v, float* __restrict__ C2,
        const float* __restrict__ bvec, int M, int affine, int c0half, int c1half) {
    const __half* W = (blockIdx.y == 0) ? W0h : (blockIdx.y == 1 ? W1h : W2h);
    void* Cv = (blockIdx.y == 0) ? C0v : (blockIdx.y == 1 ? C1v : (void*)C2);
    int ishalf = (blockIdx.y == 0) ? c0half : (blockIdx.y == 1 ? c1half : 0);

    extern __shared__ __half smem_h[];
    __half* As = smem_h;                    // [256][GM_HS]  (row-major, k contig)
    __half* Ws = smem_h + GM_MT * GM_HS;    // [128][GM_HS]  (NATURAL: [k][n], n contig)

    int tid = threadIdx.x;
    int warp = tid >> 5;
    int lane = tid & 31;

    // zero BN accumulators for the following fused GAT+BN kernel
    if (blockIdx.x == 0 && blockIdx.y == 0) {
        if (tid < 128) { g_dsum[tid] = 0.0; g_dsq[tid] = 0.0; }
        if (tid == 0) g_ticket = 0;
    }

    int wm = warp >> 1;           // 0..7  -> 32-row slab
    int wn = warp & 1;            // 0..1  -> 64-col slab
    int m0 = blockIdx.x * GM_MT;

    int qr = lane >> 2;           // 0..7
    int qc = lane & 3;            // 0..3

    unsigned ws_base = (unsigned)__cvta_generic_to_shared(Ws);

    // ---- W tile: issue cp.async FIRST so the fetch overlaps the A phase ----
    // 128 rows x 256B; 2048 chunks of 16B; 4 per thread.
#pragma unroll
    for (int it = 0; it < 4; it++) {
        int i = it * 512 + tid;            // 0..2047
        int row = i >> 4;                  // 0..127 (k index)
        int chunk = i & 15;                // 16B chunk within row
        unsigned dst = ws_base + (unsigned)row * (GM_HS * 2) + (unsigned)chunk * 16;
        const __half* src = W + row * 128 + chunk * 8;
        asm volatile("cp.async.ca.shared.global [%0], [%1], 16;\n"
                     :: "r"(dst), "l"(src));
    }
    asm volatile("cp.async.commit_group;\n");

    // ---- load full A tile (256 x 128) -> fp16 (under the W cp.async) ----
#pragma unroll
    for (int it = 0; it < 16; it++) {
        int i = it * 512 + tid;
        int row = i >> 5;
        int col = (i & 31) * 4;
        int gm = m0 + row;
        float4 v = make_float4(0.f, 0.f, 0.f, 0.f);
        if (gm < M) v = *(const float4*)(A + (long long)gm * 128 + col);
        if (affine) {
            float4 sc = *(const float4*)(g_scale + col);
            float4 sh = *(const float4*)(g_shift + col);
            v.x = fmaf(v.x, sc.x, sh.x); v.x = v.x > 0.f ? v.x : v.x * SLOPE;
            v.y = fmaf(v.y, sc.y, sh.y); v.y = v.y > 0.f ? v.y : v.y * SLOPE;
            v.z = fmaf(v.z, sc.z, sh.z); v.z = v.z > 0.f ? v.z : v.z * SLOPE;
            v.w = fmaf(v.w, sc.w, sh.w); v.w = v.w > 0.f ? v.w : v.w * SLOPE;
        }
        __half* dst = As + row * GM_HS + col;
        *(__half2*)(dst)     = __floats2half2_rn(v.x, v.y);
        *(__half2*)(dst + 2) = __floats2half2_rn(v.z, v.w);
    }
    asm volatile("cp.async.wait_group 0;\n");
    __syncthreads();

    float acc[2][8][4];
#pragma unroll
    for (int i = 0; i < 2; i++)
#pragma unroll
        for (int j = 0; j < 8; j++)
#pragma unroll
            for (int k = 0; k < 4; k++) acc[i][j][k] = 0.f;

    // ldmatrix lane-address offsets (bytes)
    unsigned as_base = (unsigned)__cvta_generic_to_shared(As);
    unsigned a_off = (unsigned)(lane & 15) * (GM_HS * 2) + (unsigned)(lane >> 4) * 16;
    unsigned b_off = a_off;

#pragma unroll
    for (int ks = 0; ks < 8; ks++) {
        int kb = ks * 16;
        unsigned a[2][4];
#pragma unroll
        for (int mi = 0; mi < 2; mi++) {
            int rb = wm * 32 + mi * 16;
            unsigned aaddr = as_base + (unsigned)rb * (GM_HS * 2) + (unsigned)kb * 2 + a_off;
            asm volatile(
                "ldmatrix.sync.aligned.m8n8.x4.shared.b16 {%0,%1,%2,%3}, [%4];\n"
                : "=r"(a[mi][0]), "=r"(a[mi][1]), "=r"(a[mi][2]), "=r"(a[mi][3])
                : "r"(aaddr));
        }
        unsigned kaddr = ws_base + (unsigned)kb * (GM_HS * 2) + b_off;
#pragma unroll
        for (int np = 0; np < 4; np++) {          // n-tile pairs: ni = 2np, 2np+1
            int n0 = wn * 64 + np * 16;
            unsigned b0, b1, b2, b3;
            asm volatile(
                "ldmatrix.sync.aligned.m8n8.x4.trans.shared.b16 {%0,%1,%2,%3}, [%4];\n"
                : "=r"(b0), "=r"(b1), "=r"(b2), "=r"(b3)
                : "r"(kaddr + (unsigned)(n0 * 2)));
#pragma unroll
            for (int mi = 0; mi < 2; mi++) {
                asm volatile(
                    "mma.sync.aligned.m16n8k16.row.col.f32.f16.f16.f32 "
                    "{%0,%1,%2,%3}, {%4,%5,%6,%7}, {%8,%9}, {%0,%1,%2,%3};\n"
                    : "+f"(acc[mi][2 * np][0]), "+f"(acc[mi][2 * np][1]),
                      "+f"(acc[mi][2 * np][2]), "+f"(acc[mi][2 * np][3])
                    : "r"(a[mi][0]), "r"(a[mi][1]), "r"(a[mi][2]), "r"(a[mi][3]),
                      "r"(b0), "r"(b1));
                asm volatile(
                    "mma.sync.aligned.m16n8k16.row.col.f32.f16.f16.f32 "
                    "{%0,%1,%2,%3}, {%4,%5,%6,%7}, {%8,%9}, {%0,%1,%2,%3};\n"
                    : "+f"(acc[mi][2 * np + 1][0]), "+f"(acc[mi][2 * np + 1][1]),
                      "+f"(acc[mi][2 * np + 1][2]), "+f"(acc[mi][2 * np + 1][3])
                    : "r"(a[mi][0]), "r"(a[mi][1]), "r"(a[mi][2]), "r"(a[mi][3]),
                      "r"(b2), "r"(b3));
            }
        }
    }

    // epilogue (accumulator layout identical to before)
    float* C = (float*)Cv;
    __half* Ch = (__half*)Cv;
#pragma unroll
    for (int mi = 0; mi < 2; mi++) {
        int r0 = m0 + wm * 32 + mi * 16 + qr;
#pragma unroll
        for (int ni = 0; ni < 8; ni++) {
            int col = wn * 64 + ni * 8 + qc * 2;
            float bx = 0.f, by = 0.f;
            if (bvec) { bx = bvec[col]; by = bvec[col + 1]; }
            if (ishalf) {
                if (r0 < M) {
                    __half2 o = __floats2half2_rn(acc[mi][ni][0] + bx, acc[mi][ni][1] + by);
                    *(__half2*)(Ch + (long long)r0 * 128 + col) = o;
                }
                if (r0 + 8 < M) {
                    __half2 o = __floats2half2_rn(acc[mi][ni][2] + bx, acc[mi][ni][3] + by);
                    *(__half2*)(Ch + (long long)(r0 + 8) * 128 + col) = o;
                }
            } else {
                if (r0 < M) {
                    float2 o; o.x = acc[mi][ni][0] + bx; o.y = acc[mi][ni][1] + by;
                    *(float2*)(C + (long long)r0 * 128 + col) = o;
                }
                if (r0 + 8 < M) {
                    float2 o; o.x = acc[mi][ni][2] + bx; o.y = acc[mi][ni][3] + by;
                    *(float2*)(C + (long long)(r0 + 8) * 128 + col) = o;
                }
            }
        }
    }
}

// ---------------- fused GATv2 edge pass + BN statistics + BN finalize ----------------
// R8 measured-best configuration: xl fp16 (gathered), xr/xres fp32 (streamed).
// Softmax without running max (scores bounded; clamp at 80 for overflow safety).
// NOTE: occupancy-critical at the 64-reg/4-CTA cliff — do not add live registers.
__device__ __forceinline__ float4 ld_h4(const __half* __restrict__ p,
                                        long long node, int lane) {
    uint2 raw = *(const uint2*)(p + node * D + lane * 4);
    float2 f01 = __half22float2(*(__half2*)&raw.x);
    float2 f23 = __half22float2(*(__half2*)&raw.y);
    return make_float4(f01.x, f01.y, f23.x, f23.y);
}

__device__ __forceinline__ float gat_score(float4 ml, float4 xr4, float4 a4) {
    float px = ml.x + xr4.x; px = px > 0.f ? px : px * SLOPE;
    float py = ml.y + xr4.y; py = py > 0.f ? py : py * SLOPE;
    float pz = ml.z + xr4.z; pz = pz > 0.f ? pz : pz * SLOPE;
    float pw = ml.w + xr4.w; pw = pw > 0.f ? pw : pw * SLOPE;
    return px * a4.x + py * a4.y + pz * a4.z + pw * a4.w;
}

__global__ void __launch_bounds__(GAT_THREADS)
k_gat_bn(const __half* __restrict__ xl, const float* __restrict__ xr,
         const float* __restrict__ xres, const float* __restrict__ att,
         const float* __restrict__ bias,
         const float* __restrict__ gamma, const float* __restrict__ beta,
         float* __restrict__ h, int N) {
    __shared__ float s_sum[128];
    __shared__ float s_sq[128];
    __shared__ int s_last;

    int tid = threadIdx.x;
    if (tid < 128) { s_sum[tid] = 0.f; s_sq[tid] = 0.f; }
    __syncthreads();

    int gwarp = blockIdx.x * (GAT_THREADS / 32) + (tid >> 5);
    int lane = tid & 31;

    float4 a4 = *(const float4*)(att + lane * 4);
    float4 b4 = *(const float4*)(bias + lane * 4);

    float lsum[4] = {0.f, 0.f, 0.f, 0.f};
    float lsq[4]  = {0.f, 0.f, 0.f, 0.f};

    for (int node = gwarp; node < N; node += GAT_WARPS) {
        float4 xr4 = *(const float4*)(xr + (long long)node * D + lane * 4);
        int beg = g_rowptr[node];
        int end = g_rowptr[node + 1];

        float s = 0.f;
        float4 acc = make_float4(0.f, 0.f, 0.f, 0.f);

        int e = beg;
        for (; e + 4 <= end; e += 4) {
            int si[4];
#pragma unroll
            for (int j = 0; j < 4; j++) si[j] = g_col[e + j];
            float4 ml[4];
#pragma unroll
            for (int j = 0; j < 4; j++) ml[j] = ld_h4(xl, si[j], lane);
            float pt[4];
#pragma unroll
            for (int j = 0; j < 4; j++) pt[j] = gat_score(ml[j], xr4, a4);
#pragma unroll
            for (int j = 0; j < 4; j++) pt[j] += __shfl_xor_sync(0xffffffffu, pt[j], 1);
#pragma unroll
            for (int j = 0; j < 4; j++) pt[j] += __shfl_xor_sync(0xffffffffu, pt[j], 2);
#pragma unroll
            for (int j = 0; j < 4; j++) pt[j] += __shfl_xor_sync(0xffffffffu, pt[j], 4);
            float p[4];
#pragma unroll
            for (int j = 0; j < 4; j++) p[j] = __expf(fminf(pt[j], 80.f));
#pragma unroll
            for (int j = 0; j < 4; j++) {
                s += p[j];
                acc.x = fmaf(p[j], ml[j].x, acc.x);
                acc.y = fmaf(p[j], ml[j].y, acc.y);
                acc.z = fmaf(p[j], ml[j].z, acc.z);
                acc.w = fmaf(p[j], ml[j].w, acc.w);
            }
        }
        for (; e < end; e++) {
            int s0 = g_col[e];
            float4 ml0 = ld_h4(xl, s0, lane);
            float pt = gat_score(ml0, xr4, a4);
            pt += __shfl_xor_sync(0xffffffffu, pt, 1);
            pt += __shfl_xor_sync(0xffffffffu, pt, 2);
            pt += __shfl_xor_sync(0xffffffffu, pt, 4);
            float p = __expf(fminf(pt, 80.f));
            s += p;
            acc.x = fmaf(p, ml0.x, acc.x);
            acc.y = fmaf(p, ml0.y, acc.y);
            acc.z = fmaf(p, ml0.z, acc.z);
            acc.w = fmaf(p, ml0.w, acc.w);
        }

        float inv = 1.f / s;
        float4 r4 = *(const float4*)(xres + (long long)node * D + lane * 4);
        float4 o;
        o.x = acc.x * inv + b4.x + r4.x;
        o.y = acc.y * inv + b4.y + r4.y;
        o.z = acc.z * inv + b4.z + r4.z;
        o.w = acc.w * inv + b4.w + r4.w;
        *(float4*)(h + (long long)node * D + lane * 4) = o;

        lsum[0] += o.x; lsq[0] += o.x * o.x;
        lsum[1] += o.y; lsq[1] += o.y * o.y;
        lsum[2] += o.z; lsq[2] += o.z * o.z;
        lsum[3] += o.w; lsq[3] += o.w * o.w;
    }

    int c = lane * 4;
#pragma unroll
    for (int j = 0; j < 4; j++) {
        atomicAdd(&s_sum[c + j], lsum[j]);
        atomicAdd(&s_sq[c + j],  lsq[j]);
    }
    __syncthreads();

    if (tid < 128) {
        atomicAdd(&g_dsum[tid], (double)s_sum[tid]);
        atomicAdd(&g_dsq[tid],  (double)s_sq[tid]);
    }
    __threadfence();
    __syncthreads();
    if (tid == 0) {
        int t = atomicAdd(&g_ticket, 1);
        s_last = (t == (int)gridDim.x - 1) ? 1 : 0;
    }
    __syncthreads();

    if (s_last && tid < 128) {
        double mean = __ldcg(&g_dsum[tid]) / (double)N;
        double var  = __ldcg(&g_dsq[tid]) / (double)N - mean * mean;
        float inv = rsqrtf((float)var + BN_EPS);
        float sc = gamma[tid] * inv;
        g_scale[tid] = sc;
        g_shift[tid] = beta[tid] - (float)mean * sc;
    }
}

// ---------------- launch ----------------
extern "C" void kernel_launch(void* const* d_in, const int* in_sizes, int n_in,
                              void* d_out, int out_size) {
    const float* x     = (const float*)d_in[0];
    const void*  ei    = d_in[1];
    const float* Wl    = (const float*)d_in[2];
    const float* Wr    = (const float*)d_in[3];
    const float* att   = (const float*)d_in[4];
    const float* bias  = (const float*)d_in[5];
    const float* Wres  = (const float*)d_in[6];
    const float* gamma = (const float*)d_in[7];
    const float* beta  = (const float*)d_in[8];
    const float* Wout  = (const float*)d_in[9];
    const float* bout  = (const float*)d_in[10];
    int N = in_sizes[0] / D;
    int E = in_sizes[1] / 2;
    float* out = (float*)d_out;

    __half *p_xlh, *p_w16;
    float *p_xr, *p_xres, *p_h;
    cudaGetSymbolAddress((void**)&p_xlh, g_xl_h);
    cudaGetSymbolAddress((void**)&p_w16, g_w16);
    cudaGetSymbolAddress((void**)&p_xr, g_xr);
    cudaGetSymbolAddress((void**)&p_xres, g_xres);
    cudaGetSymbolAddress((void**)&p_h, g_h);

    static cudaStream_t s2 = []() {
        cudaStream_t s; cudaStreamCreateWithFlags(&s, cudaStreamNonBlocking); return s;
    }();
    static cudaEvent_t ev_fork = []() {
        cudaEvent_t e; cudaEventCreateWithFlags(&e, cudaEventDisableTiming); return e;
    }();
    static cudaEvent_t ev_csr = []() {
        cudaEvent_t e; cudaEventCreateWithFlags(&e, cudaEventDisableTiming); return e;
    }();
    static bool attr_ok = []() {
        cudaFuncSetAttribute(k_gemm3, cudaFuncAttributeMaxDynamicSharedMemorySize,
                             GM_SMEM_BYTES);
        return true;
    }();
    (void)attr_ok;

    int Et = E + N;
    int nb = (N + 1023) / 1024;

    int mtiles = (N + GM_MT - 1) / GM_MT;
    dim3 g3(mtiles, 3);
    dim3 g1(mtiles, 1);

    // fp16 weight slot pointers
    const __half* wl16 = p_w16;
    const __half* wr16 = p_w16 + 3 * D * D;
    const __half* wres16 = p_w16 + 6 * D * D;
    const __half* wout16 = p_w16 + 9 * D * D;

    // fork: CSR chain on s2 (enqueued FIRST so ncu -s lands on hot kernels),
    // overlapped with weight conversion + layer-0 GEMM on the main stream.
    cudaEventRecord(ev_fork, 0);
    cudaStreamWaitEvent(s2, ev_fork, 0);
    k_count<<<(Et + 255) / 256, 256, 0, s2>>>(ei, E, N);
    k_scan1<<<nb, 1024, 0, s2>>>(N);
    k_scan3<<<nb, 1024, 0, s2>>>(N);
    k_scatter<<<(Et + 255) / 256, 256, 0, s2>>>(ei, E, N);
    cudaEventRecord(ev_csr, s2);

    // weight conversion: 10*16384/2 = 81920 half2 -> 320 blocks x 256 thr
    k_wconv<<<320, 256>>>(Wl, Wr, Wres, Wout);
    k_gemm3<<<g3, 512, GM_SMEM_BYTES>>>(x, wl16, wr16, wres16,
                                        p_xlh, p_xr, p_xres, nullptr, N, 0, 1, 0);
    cudaStreamWaitEvent(0, ev_csr, 0);  // join CSR before first edge pass

    const float* xin = x;
    for (int l = 0; l < 3; l++) {
        if (l > 0) {
            k_gemm3<<<g3, 512, GM_SMEM_BYTES>>>(xin,
                                                wl16 + l * D * D, wr16 + l * D * D,
                                                wres16 + l * D * D,
                                                p_xlh, p_xr, p_xres, nullptr, N, 1, 1, 0);
        }
        k_gat_bn<<<GAT_BLOCKS, GAT_THREADS>>>(p_xlh, p_xr, p_xres, att + l * D,
                                              bias + l * D, gamma + l * D,
                                              beta + l * D, p_h, N);
        xin = p_h;
    }
    k_gemm3<<<g1, 512, GM_SMEM_BYTES>>>(p_h, wout16, wout16, wout16,
                                        out, out, out, bout, N, 1, 0, 0);
}

// round 17
// speedup vs baseline: 1.0220x; 1.0031x over previous
#include <cuda_runtime.h>
#include <cuda_fp16.h>
#include <math.h>

#define D 128
#define SLOPE 0.2f
#define BN_EPS 1e-5f
#define MAXN 50048
#define MAXET 901120

// GEMM tile config: 256-row M tile, full K=128 in smem (fp16)
#define GM_MT 256
#define GM_HS 136   // half-element stride (272B rows: bank stride 4, conflict-free)
#define GM_SMEM_BYTES ((GM_MT * GM_HS + 128 * GM_HS) * 2)

// GAT kernel launch shape: pooled strided warp scheduling
#define GAT_BLOCKS 592
#define GAT_THREADS 256
#define GAT_WARPS (GAT_BLOCKS * (GAT_THREADS / 32))

// leaky_relu(v) = max(v, SLOPE*v) exactly, for SLOPE in (0,1): FMUL+FMNMX
#define LEAKY(v) fmaxf((v), (v) * SLOPE)

// ---------------- scratch (static device globals: allocation-free) ----------------
__device__ __align__(16) __half g_xl_h[MAXN * D];   // fp16 source-transform (gathered)
__device__ __align__(16) float g_xr[MAXN * D];
__device__ __align__(16) float g_xres[MAXN * D];
__device__ __align__(16) float g_h[MAXN * D];
__device__ __align__(16) __half g_w16[10 * D * D];  // pre-converted fp16 weights
__device__ int g_deg[MAXN];
__device__ int g_cursor[MAXN];
__device__ int g_rowptr[MAXN + 1];
__device__ int g_col[MAXET];
__device__ int g_bsum[64];
__device__ double g_dsum[D];
__device__ double g_dsq[D];
__device__ __align__(16) float g_scale[D];
__device__ __align__(16) float g_shift[D];
__device__ int g_ticket;

// int64-vs-int32 probe: odd 32-bit words of the first 8 values all zero => int64.
__device__ __forceinline__ int probe_is64(const unsigned int* __restrict__ p) {
    unsigned int o = 0;
#pragma unroll
    for (int j = 1; j < 16; j += 2) o |= p[j];
    return o == 0u;
}

// ---------------- weight pre-conversion: fp32 -> fp16 (same _rn rounding) --------
__global__ void k_wconv(const float* __restrict__ Wl, const float* __restrict__ Wr,
                        const float* __restrict__ Wres, const float* __restrict__ Wout) {
    int i = (blockIdx.x * blockDim.x + threadIdx.x) * 2;   // half2 granularity
    int per = 3 * D * D;
    const float* src;
    int off;
    if (i < per)            { src = Wl;   off = i; }
    else if (i < 2 * per)   { src = Wr;   off = i - per; }
    else if (i < 3 * per)   { src = Wres; off = i - 2 * per; }
    else if (i < 3 * per + D * D) { src = Wout; off = i - 3 * per; }
    else return;
    float2 v = *(const float2*)(src + off);
    *(__half2*)(g_w16 + i) = __floats2half2_rn(v.x, v.y);
}

// ---------------- CSR build ----------------
__global__ void k_count(const void* __restrict__ ei, int E, int N) {
    __shared__ int s64;
    if (threadIdx.x == 0) s64 = probe_is64((const unsigned int*)ei);
    __syncthreads();
    int is64 = s64;
    int t = blockIdx.x * blockDim.x + threadIdx.x;
    int Et = E + N;
    if (t >= Et) return;
    int d;
    if (t < E) {
        d = is64 ? (int)((const long long*)ei)[(long long)E + t]
                 : ((const int*)ei)[E + t];
    } else {
        d = t - E;  // self loop
    }
    atomicAdd(&g_deg[d], 1);
}

__global__ void k_scan1(int N) {
    __shared__ int s[1024];
    int tid = threadIdx.x;
    int i = blockIdx.x * 1024 + tid;
    int v = (i < N) ? g_deg[i] : 0;
    if (i < N) { g_deg[i] = 0; g_cursor[i] = 0; }  // restore zeros for next call
    s[tid] = v;
    __syncthreads();
    for (int off = 1; off < 1024; off <<= 1) {
        int t = 0;
        if (tid >= off) t = s[tid - off];
        __syncthreads();
        if (tid >= off) s[tid] += t;
        __syncthreads();
    }
    if (i < N) g_rowptr[i + 1] = s[tid];
    if (tid == 1023) g_bsum[blockIdx.x] = s[1023];
}

__global__ void k_scan3(int N) {
    __shared__ int sbase;
    if (threadIdx.x == 0) {
        int acc = 0;
        for (int b = 0; b < blockIdx.x; b++) acc += g_bsum[b];
        sbase = acc;
    }
    __syncthreads();
    int i = blockIdx.x * 1024 + threadIdx.x;
    if (i < N) g_rowptr[i + 1] += sbase;
    if (i == 0) g_rowptr[0] = 0;
}

__global__ void k_scatter(const void* __restrict__ ei, int E, int N) {
    __shared__ int s64;
    if (threadIdx.x == 0) s64 = probe_is64((const unsigned int*)ei);
    __syncthreads();
    int is64 = s64;
    int t = blockIdx.x * blockDim.x + threadIdx.x;
    int Et = E + N;
    if (t >= Et) return;
    int s, d;
    if (t < E) {
        if (is64) {
            s = (int)((const long long*)ei)[t];
            d = (int)((const long long*)ei)[(long long)E + t];
        } else {
            s = ((const int*)ei)[t];
            d = ((const int*)ei)[E + t];
        }
    } else {
        s = d = t - E;
    }
    int pos = g_rowptr[d] + atomicAdd(&g_cursor[d], 1);
    g_col[pos] = s;
}

// ---------------- fp16 tensor-core GEMM (m16n8k16, whole-K, single sync) ----------------
// C[M,128] = act(A)[M,128] @ W[128,128] (+bias)
// Block: 512 threads (16 warps, 8x2), C tile 256x128, warp tile 32x64.
// W: pre-converted fp16 via cp.async (overlapped with A phase).
// A phase: affine params hoisted (col is it-invariant), leaky via FMNMX.
__global__ void __launch_bounds__(512, 1)
k_gemm3(const float* __restrict__ A,
        const __half* __restrict__ W0h, const __half* __restrict__ W1h,
        const __half* __restrict__ W2h,
        void* __restrict__ C0v, void* __restrict__ C1v, float* __restrict__ C2,
        const float* __restrict__ bvec, int M, int affine, int c0half, int c1half) {
    const __half* W = (blockIdx.y == 0) ? W0h : (blockIdx.y == 1 ? W1h : W2h);
    void* Cv = (blockIdx.y == 0) ? C0v : (blockIdx.y == 1 ? C1v : (void*)C2);
    int ishalf = (blockIdx.y == 0) ? c0half : (blockIdx.y == 1 ? c1half : 0);

    extern __shared__ __half smem_h[];
    __half* As = smem_h;                    // [256][GM_HS]  (row-major, k contig)
    __half* Ws = smem_h + GM_MT * GM_HS;    // [128][GM_HS]  (NATURAL: [k][n], n contig)

    int tid = threadIdx.x;
    int warp = tid >> 5;
    int lane = tid & 31;

    // zero BN accumulators for the following fused GAT+BN kernel
    if (blockIdx.x == 0 && blockIdx.y == 0) {
        if (tid < 128) { g_dsum[tid] = 0.0; g_dsq[tid] = 0.0; }
        if (tid == 0) g_ticket = 0;
    }

    int wm = warp >> 1;           // 0..7  -> 32-row slab
    int wn = warp & 1;            // 0..1  -> 64-col slab
    int m0 = blockIdx.x * GM_MT;

    int qr = lane >> 2;           // 0..7
    int qc = lane & 3;            // 0..3

    unsigned ws_base = (unsigned)__cvta_generic_to_shared(Ws);

    // ---- W tile: issue cp.async FIRST so the fetch overlaps the A phase ----
#pragma unroll
    for (int it = 0; it < 4; it++) {
        int i = it * 512 + tid;            // 0..2047
        int row = i >> 4;                  // 0..127 (k index)
        int chunk = i & 15;                // 16B chunk within row
        unsigned dst = ws_base + (unsigned)row * (GM_HS * 2) + (unsigned)chunk * 16;
        const __half* src = W + row * 128 + chunk * 8;
        asm volatile("cp.async.ca.shared.global [%0], [%1], 16;\n"
                     :: "r"(dst), "l"(src));
    }
    asm volatile("cp.async.commit_group;\n");

    // ---- load full A tile (256 x 128) -> fp16 (under the W cp.async) ----
    // col = ((it*512+tid)&31)*4 is it-invariant: hoist affine params out of the loop.
    int acol = (tid & 31) * 4;
    float4 sc4 = make_float4(1.f, 1.f, 1.f, 1.f);
    float4 sh4 = make_float4(0.f, 0.f, 0.f, 0.f);
    if (affine) {
        sc4 = *(const float4*)(g_scale + acol);
        sh4 = *(const float4*)(g_shift + acol);
    }
#pragma unroll
    for (int it = 0; it < 16; it++) {
        int i = it * 512 + tid;
        int row = i >> 5;
        int gm = m0 + row;
        float4 v = make_float4(0.f, 0.f, 0.f, 0.f);
        if (gm < M) v = *(const float4*)(A + (long long)gm * 128 + acol);
        if (affine) {
            v.x = fmaf(v.x, sc4.x, sh4.x); v.x = LEAKY(v.x);
            v.y = fmaf(v.y, sc4.y, sh4.y); v.y = LEAKY(v.y);
            v.z = fmaf(v.z, sc4.z, sh4.z); v.z = LEAKY(v.z);
            v.w = fmaf(v.w, sc4.w, sh4.w); v.w = LEAKY(v.w);
        }
        __half* dst = As + row * GM_HS + acol;
        *(__half2*)(dst)     = __floats2half2_rn(v.x, v.y);
        *(__half2*)(dst + 2) = __floats2half2_rn(v.z, v.w);
    }
    asm volatile("cp.async.wait_group 0;\n");
    __syncthreads();

    float acc[2][8][4];
#pragma unroll
    for (int i = 0; i < 2; i++)
#pragma unroll
        for (int j = 0; j < 8; j++)
#pragma unroll
            for (int k = 0; k < 4; k++) acc[i][j][k] = 0.f;

    // ldmatrix lane-address offsets (bytes)
    unsigned as_base = (unsigned)__cvta_generic_to_shared(As);
    unsigned a_off = (unsigned)(lane & 15) * (GM_HS * 2) + (unsigned)(lane >> 4) * 16;
    unsigned b_off = a_off;

#pragma unroll
    for (int ks = 0; ks < 8; ks++) {
        int kb = ks * 16;
        unsigned a[2][4];
#pragma unroll
        for (int mi = 0; mi < 2; mi++) {
            int rb = wm * 32 + mi * 16;
            unsigned aaddr = as_base + (unsigned)rb * (GM_HS * 2) + (unsigned)kb * 2 + a_off;
            asm volatile(
                "ldmatrix.sync.aligned.m8n8.x4.shared.b16 {%0,%1,%2,%3}, [%4];\n"
                : "=r"(a[mi][0]), "=r"(a[mi][1]), "=r"(a[mi][2]), "=r"(a[mi][3])
                : "r"(aaddr));
        }
        unsigned kaddr = ws_base + (unsigned)kb * (GM_HS * 2) + b_off;
#pragma unroll
        for (int np = 0; np < 4; np++) {          // n-tile pairs: ni = 2np, 2np+1
            int n0 = wn * 64 + np * 16;
            unsigned b0, b1, b2, b3;
            asm volatile(
                "ldmatrix.sync.aligned.m8n8.x4.trans.shared.b16 {%0,%1,%2,%3}, [%4];\n"
                : "=r"(b0), "=r"(b1), "=r"(b2), "=r"(b3)
                : "r"(kaddr + (unsigned)(n0 * 2)));
#pragma unroll
            for (int mi = 0; mi < 2; mi++) {
                asm volatile(
                    "mma.sync.aligned.m16n8k16.row.col.f32.f16.f16.f32 "
                    "{%0,%1,%2,%3}, {%4,%5,%6,%7}, {%8,%9}, {%0,%1,%2,%3};\n"
                    : "+f"(acc[mi][2 * np][0]), "+f"(acc[mi][2 * np][1]),
                      "+f"(acc[mi][2 * np][2]), "+f"(acc[mi][2 * np][3])
                    : "r"(a[mi][0]), "r"(a[mi][1]), "r"(a[mi][2]), "r"(a[mi][3]),
                      "r"(b0), "r"(b1));
                asm volatile(
                    "mma.sync.aligned.m16n8k16.row.col.f32.f16.f16.f32 "
                    "{%0,%1,%2,%3}, {%4,%5,%6,%7}, {%8,%9}, {%0,%1,%2,%3};\n"
                    : "+f"(acc[mi][2 * np + 1][0]), "+f"(acc[mi][2 * np + 1][1]),
                      "+f"(acc[mi][2 * np + 1][2]), "+f"(acc[mi][2 * np + 1][3])
                    : "r"(a[mi][0]), "r"(a[mi][1]), "r"(a[mi][2]), "r"(a[mi][3]),
                      "r"(b2), "r"(b3));
            }
        }
    }

    // epilogue (accumulator layout identical to before)
    float* C = (float*)Cv;
    __half* Ch = (__half*)Cv;
#pragma unroll
    for (int mi = 0; mi < 2; mi++) {
        int r0 = m0 + wm * 32 + mi * 16 + qr;
#pragma unroll
        for (int ni = 0; ni < 8; ni++) {
            int col = wn * 64 + ni * 8 + qc * 2;
            float bx = 0.f, by = 0.f;
            if (bvec) { bx = bvec[col]; by = bvec[col + 1]; }
            if (ishalf) {
                if (r0 < M) {
                    __half2 o = __floats2half2_rn(acc[mi][ni][0] + bx, acc[mi][ni][1] + by);
                    *(__half2*)(Ch + (long long)r0 * 128 + col) = o;
                }
                if (r0 + 8 < M) {
                    __half2 o = __floats2half2_rn(acc[mi][ni][2] + bx, acc[mi][ni][3] + by);
                    *(__half2*)(Ch + (long long)(r0 + 8) * 128 + col) = o;
                }
            } else {
                if (r0 < M) {
                    float2 o; o.x = acc[mi][ni][0] + bx; o.y = acc[mi][ni][1] + by;
                    *(float2*)(C + (long long)r0 * 128 + col) = o;
                }
                if (r0 + 8 < M) {
                    float2 o; o.x = acc[mi][ni][2] + bx; o.y = acc[mi][ni][3] + by;
                    *(float2*)(C + (long long)(r0 + 8) * 128 + col) = o;
                }
            }
        }
    }
}

// ---------------- fused GATv2 edge pass + BN statistics + BN finalize ----------------
// R8 measured-best configuration: xl fp16 (gathered), xr/xres fp32 (streamed).
// Softmax without running max (scores bounded; clamp at 80 for overflow safety).
// Leaky via FMNMX (max(v, 0.2v)) — register-neutral instruction cut.
// NOTE: occupancy-critical at the 64-reg/4-CTA cliff — do not add live registers.
__device__ __forceinline__ float4 ld_h4(const __half* __restrict__ p,
                                        long long node, int lane) {
    uint2 raw = *(const uint2*)(p + node * D + lane * 4);
    float2 f01 = __half22float2(*(__half2*)&raw.x);
    float2 f23 = __half22float2(*(__half2*)&raw.y);
    return make_float4(f01.x, f01.y, f23.x, f23.y);
}

__device__ __forceinline__ float gat_score(float4 ml, float4 xr4, float4 a4) {
    float px = LEAKY(ml.x + xr4.x);
    float py = LEAKY(ml.y + xr4.y);
    float pz = LEAKY(ml.z + xr4.z);
    float pw = LEAKY(ml.w + xr4.w);
    return px * a4.x + py * a4.y + pz * a4.z + pw * a4.w;
}

__global__ void __launch_bounds__(GAT_THREADS)
k_gat_bn(const __half* __restrict__ xl, const float* __restrict__ xr,
         const float* __restrict__ xres, const float* __restrict__ att,
         const float* __restrict__ bias,
         const float* __restrict__ gamma, const float* __restrict__ beta,
         float* __restrict__ h, int N) {
    __shared__ float s_sum[128];
    __shared__ float s_sq[128];
    __shared__ int s_last;

    int tid = threadIdx.x;
    if (tid < 128) { s_sum[tid] = 0.f; s_sq[tid] = 0.f; }
    __syncthreads();

    int gwarp = blockIdx.x * (GAT_THREADS / 32) + (tid >> 5);
    int lane = tid & 31;

    float4 a4 = *(const float4*)(att + lane * 4);
    float4 b4 = *(const float4*)(bias + lane * 4);

    float lsum[4] = {0.f, 0.f, 0.f, 0.f};
    float lsq[4]  = {0.f, 0.f, 0.f, 0.f};

    for (int node = gwarp; node < N; node += GAT_WARPS) {
        float4 xr4 = *(const float4*)(xr + (long long)node * D + lane * 4);
        int beg = g_rowptr[node];
        int end = g_rowptr[node + 1];

        float s = 0.f;
        float4 acc = make_float4(0.f, 0.f, 0.f, 0.f);

        int e = beg;
        for (; e + 4 <= end; e += 4) {
            int si[4];
#pragma unroll
            for (int j = 0; j < 4; j++) si[j] = g_col[e + j];
            float4 ml[4];
#pragma unroll
            for (int j = 0; j < 4; j++) ml[j] = ld_h4(xl, si[j], lane);
            float pt[4];
#pragma unroll
            for (int j = 0; j < 4; j++) pt[j] = gat_score(ml[j], xr4, a4);
#pragma unroll
            for (int j = 0; j < 4; j++) pt[j] += __shfl_xor_sync(0xffffffffu, pt[j], 1);
#pragma unroll
            for (int j = 0; j < 4; j++) pt[j] += __shfl_xor_sync(0xffffffffu, pt[j], 2);
#pragma unroll
            for (int j = 0; j < 4; j++) pt[j] += __shfl_xor_sync(0xffffffffu, pt[j], 4);
            float p[4];
#pragma unroll
            for (int j = 0; j < 4; j++) p[j] = __expf(fminf(pt[j], 80.f));
#pragma unroll
            for (int j = 0; j < 4; j++) {
                s += p[j];
                acc.x = fmaf(p[j], ml[j].x, acc.x);
                acc.y = fmaf(p[j], ml[j].y, acc.y);
                acc.z = fmaf(p[j], ml[j].z, acc.z);
                acc.w = fmaf(p[j], ml[j].w, acc.w);
            }
        }
        for (; e < end; e++) {
            int s0 = g_col[e];
            float4 ml0 = ld_h4(xl, s0, lane);
            float pt = gat_score(ml0, xr4, a4);
            pt += __shfl_xor_sync(0xffffffffu, pt, 1);
            pt += __shfl_xor_sync(0xffffffffu, pt, 2);
            pt += __shfl_xor_sync(0xffffffffu, pt, 4);
            float p = __expf(fminf(pt, 80.f));
            s += p;
            acc.x = fmaf(p, ml0.x, acc.x);
            acc.y = fmaf(p, ml0.y, acc.y);
            acc.z = fmaf(p, ml0.z, acc.z);
            acc.w = fmaf(p, ml0.w, acc.w);
        }

        float inv = 1.f / s;
        float4 r4 = *(const float4*)(xres + (long long)node * D + lane * 4);
        float4 o;
        o.x = acc.x * inv + b4.x + r4.x;
        o.y = acc.y * inv + b4.y + r4.y;
        o.z = acc.z * inv + b4.z + r4.z;
        o.w = acc.w * inv + b4.w + r4.w;
        *(float4*)(h + (long long)node * D + lane * 4) = o;

        lsum[0] += o.x; lsq[0] += o.x * o.x;
        lsum[1] += o.y; lsq[1] += o.y * o.y;
        lsum[2] += o.z; lsq[2] += o.z * o.z;
        lsum[3] += o.w; lsq[3] += o.w * o.w;
    }

    int c = lane * 4;
#pragma unroll
    for (int j = 0; j < 4; j++) {
        atomicAdd(&s_sum[c + j], lsum[j]);
        atomicAdd(&s_sq[c + j],  lsq[j]);
    }
    __syncthreads();

    if (tid < 128) {
        atomicAdd(&g_dsum[tid], (double)s_sum[tid]);
        atomicAdd(&g_dsq[tid],  (double)s_sq[tid]);
    }
    __threadfence();
    __syncthreads();
    if (tid == 0) {
        int t = atomicAdd(&g_ticket, 1);
        s_last = (t == (int)gridDim.x - 1) ? 1 : 0;
    }
    __syncthreads();

    if (s_last && tid < 128) {
        double mean = __ldcg(&g_dsum[tid]) / (double)N;
        double var  = __ldcg(&g_dsq[tid]) / (double)N - mean * mean;
        float inv = rsqrtf((float)var + BN_EPS);
        float sc = gamma[tid] * inv;
        g_scale[tid] = sc;
        g_shift[tid] = beta[tid] - (float)mean * sc;
    }
}

// ---------------- launch ----------------
extern "C" void kernel_launch(void* const* d_in, const int* in_sizes, int n_in,
                              void* d_out, int out_size) {
    const float* x     = (const float*)d_in[0];
    const void*  ei    = d_in[1];
    const float* Wl    = (const float*)d_in[2];
    const float* Wr    = (const float*)d_in[3];
    const float* att   = (const float*)d_in[4];
    const float* bias  = (const float*)d_in[5];
    const float* Wres  = (const float*)d_in[6];
    const float* gamma = (const float*)d_in[7];
    const float* beta  = (const float*)d_in[8];
    const float* Wout  = (const float*)d_in[9];
    const float* bout  = (const float*)d_in[10];
    int N = in_sizes[0] / D;
    int E = in_sizes[1] / 2;
    float* out = (float*)d_out;

    __half *p_xlh, *p_w16;
    float *p_xr, *p_xres, *p_h;
    cudaGetSymbolAddress((void**)&p_xlh, g_xl_h);
    cudaGetSymbolAddress((void**)&p_w16, g_w16);
    cudaGetSymbolAddress((void**)&p_xr, g_xr);
    cudaGetSymbolAddress((void**)&p_xres, g_xres);
    cudaGetSymbolAddress((void**)&p_h, g_h);

    static cudaStream_t s2 = []() {
        cudaStream_t s; cudaStreamCreateWithFlags(&s, cudaStreamNonBlocking); return s;
    }();
    static cudaEvent_t ev_fork = []() {
        cudaEvent_t e; cudaEventCreateWithFlags(&e, cudaEventDisableTiming); return e;
    }();
    static cudaEvent_t ev_csr = []() {
        cudaEvent_t e; cudaEventCreateWithFlags(&e, cudaEventDisableTiming); return e;
    }();
    static bool attr_ok = []() {
        cudaFuncSetAttribute(k_gemm3, cudaFuncAttributeMaxDynamicSharedMemorySize,
                             GM_SMEM_BYTES);
        return true;
    }();
    (void)attr_ok;

    int Et = E + N;
    int nb = (N + 1023) / 1024;

    int mtiles = (N + GM_MT - 1) / GM_MT;
    dim3 g3(mtiles, 3);
    dim3 g1(mtiles, 1);

    // fp16 weight slot pointers
    const __half* wl16 = p_w16;
    const __half* wr16 = p_w16 + 3 * D * D;
    const __half* wres16 = p_w16 + 6 * D * D;
    const __half* wout16 = p_w16 + 9 * D * D;

    // fork: CSR chain on s2, overlapped with weight conversion + layer-0 GEMM.
    cudaEventRecord(ev_fork, 0);
    cudaStreamWaitEvent(s2, ev_fork, 0);
    k_count<<<(Et + 255) / 256, 256, 0, s2>>>(ei, E, N);
    k_scan1<<<nb, 1024, 0, s2>>>(N);
    k_scan3<<<nb, 1024, 0, s2>>>(N);
    k_scatter<<<(Et + 255) / 256, 256, 0, s2>>>(ei, E, N);
    cudaEventRecord(ev_csr, s2);

    // weight conversion: 10*16384/2 = 81920 half2 -> 320 blocks x 256 thr
    k_wconv<<<320, 256>>>(Wl, Wr, Wres, Wout);
    k_gemm3<<<g3, 512, GM_SMEM_BYTES>>>(x, wl16, wr16, wres16,
                                        p_xlh, p_xr, p_xres, nullptr, N, 0, 1, 0);
    cudaStreamWaitEvent(0, ev_csr, 0);  // join CSR before first edge pass

    const float* xin = x;
    for (int l = 0; l < 3; l++) {
        if (l > 0) {
            k_gemm3<<<g3, 512, GM_SMEM_BYTES>>>(xin,
                                                wl16 + l * D * D, wr16 + l * D * D,
                                                wres16 + l * D * D,
                                                p_xlh, p_xr, p_xres, nullptr, N, 1, 1, 0);
        }
        k_gat_bn<<<GAT_BLOCKS, GAT_THREADS>>>(p_xlh, p_xr, p_xres, att + l * D,
                                              bias + l * D, gamma + l * D,
                                              beta + l * D, p_h, N);
        xin = p_h;
    }
    k_gemm3<<<g1, 512, GM_SMEM_BYTES>>>(p_h, wout16, wout16, wout16,
                                        out, out, out, bout, N, 1, 0, 0);
}